// round 9
// baseline (speedup 1.0000x reference)
#include <cuda_runtime.h>
#include <cuda_fp16.h>

#define DIM 300
#define C 16
#define NPTS 1048576u   // 2^20
#define PLANE (DIM * DIM)

// Quad-texel fp16 scratch: block (o, y, x) = 128B holding ALL 4 bilinear
// corners for all 16 channels, chunked per channel-pair:
//   uint4 chunk j (j=0..7), 16B = halves[8]:
//     [0..3] = ch 2j   : { v[y][x], v[y][x1], v[y1][x], v[y1][x1] }
//     [4..7] = ch 2j+1 : { same 4 corners }
//   (x1 = min(x+1,DIM-1), y1 = min(y+1,DIM-1), pre-clamped at build.)
// Line block (o, j) = 64B: uint2 chunk j = { ch 2j: half2(l[j], l[j1]),
//                                            ch 2j+1: half2(l[j], l[j1]) }.
// o=0 -> (plane_yz, line_x), o=1 -> (plane_xz, line_y), o=2 -> (plane_xy, line_z)
__device__ __align__(128) __half g_quad[3 * PLANE * 4 * C];  // 34.56 MB
__device__ __align__(128) __half g_lineq[3 * DIM * 2 * C];   // 57.6 KB

__global__ void build_kernel(const float* __restrict__ pxy,
                             const float* __restrict__ pyz,
                             const float* __restrict__ pxz,
                             const float* __restrict__ lx,
                             const float* __restrict__ ly,
                             const float* __restrict__ lz) {
    int id = blockIdx.x * blockDim.x + threadIdx.x;
    if (id < 3 * PLANE) {
        int p = id / PLANE;
        int pos = id - p * PLANE;        // y*DIM + x
        int y = pos / DIM;
        int x = pos - y * DIM;
        int dx = (x < DIM - 1) ? 1 : 0;
        int dy = (y < DIM - 1) ? DIM : 0;
        const float* src = (p == 0) ? pyz : (p == 1) ? pxz : pxy;
        union { __half2 h2[32]; uint4 u[8]; } pk;
#pragma unroll
        for (int c = 0; c < C; c++) {
            const float* s = src + c * PLANE + pos;
            float a00 = __ldg(s);
            float a01 = __ldg(s + dx);
            float a10 = __ldg(s + dy);
            float a11 = __ldg(s + dy + dx);
            pk.h2[2 * c]     = __floats2half2_rn(a00, a01);
            pk.h2[2 * c + 1] = __floats2half2_rn(a10, a11);
        }
        uint4* dst = reinterpret_cast<uint4*>(g_quad) + (size_t)id * 8;
#pragma unroll
        for (int j = 0; j < 8; j++) dst[j] = pk.u[j];
    } else if (id < 3 * PLANE + 3 * DIM) {
        int r = id - 3 * PLANE;
        int p = r / DIM;
        int pos = r - p * DIM;
        int dx = (pos < DIM - 1) ? 1 : 0;
        const float* src = (p == 0) ? lx : (p == 1) ? ly : lz;
        union { __half2 h2[16]; uint2 u[8]; } pk;
#pragma unroll
        for (int c = 0; c < C; c++) {
            float a = __ldg(&src[c * DIM + pos]);
            float b = __ldg(&src[c * DIM + pos + dx]);
            pk.h2[c] = __floats2half2_rn(a, b);
        }
        uint2* dst = reinterpret_cast<uint2*>(g_lineq) + (size_t)r * 8;
#pragma unroll
        for (int j = 0; j < 8; j++) dst[j] = pk.u[j];
    }
}

// Decode task id -> quad uint4 offset, line uint2 offset, weights.
// No clamps at sample time: coords strictly in [-1,1) => x0,y0,j0 <= DIM-2;
// the +1 neighbors are pre-clamped inside the scratch blocks.
__device__ __forceinline__ void decode(unsigned id,
                                       const float2* __restrict__ coords_plane,
                                       const float2* __restrict__ coords_line,
                                       unsigned& qoff, unsigned& loff,
                                       float& wx, float& wy, float& wl) {
    unsigned j = id & 7u;
    unsigned pt = id >> 3;
    unsigned o = pt >> 20;
    unsigned n = pt & (NPTS - 1u);
    unsigned po = (o == 2u) ? 0u : o + 1u;

    float2 pc = __ldg(&coords_plane[po * NPTS + n]);
    float2 lc = __ldg(&coords_line[o * NPTS + n]);

    const float S = 0.5f * (DIM - 1);
    float ix = (pc.x + 1.0f) * S;
    float iy = (pc.y + 1.0f) * S;
    int x0 = (int)ix;                 // trunc == floor (ix >= 0)
    int y0 = (int)iy;
    wx = ix - (float)x0;
    wy = iy - (float)y0;
    qoff = (o * (unsigned)PLANE + (unsigned)(y0 * DIM + x0)) * 8u + j;

    float iyl = (lc.y + 1.0f) * S;
    int j0 = (int)iyl;
    wl = iyl - (float)j0;
    loff = (o * (unsigned)DIM + (unsigned)j0) * 8u + j;
}

// Combine one task's quad (2 channels x 4 corners) + line taps -> float2.
__device__ __forceinline__ float2 combine(uint4 q, uint2 l,
                                          float wx, float wy, float wl) {
    const __half2* h = reinterpret_cast<const __half2*>(&q);
    const __half2* hl = reinterpret_cast<const __half2*>(&l);
    float2 r;
    {   // channel a
        float2 f0 = __half22float2(h[0]);   // (v00, v01)
        float2 f1 = __half22float2(h[1]);   // (v10, v11)
        float2 fl = __half22float2(hl[0]);  // (l0, l1)
        float vx0 = fmaf(wx, f0.y - f0.x, f0.x);
        float vx1 = fmaf(wx, f1.y - f1.x, f1.x);
        float v   = fmaf(wy, vx1 - vx0, vx0);
        float lv  = fmaf(wl, fl.y - fl.x, fl.x);
        r.x = v * lv;
    }
    {   // channel b
        float2 f0 = __half22float2(h[2]);
        float2 f1 = __half22float2(h[3]);
        float2 fl = __half22float2(hl[1]);
        float vx0 = fmaf(wx, f0.y - f0.x, f0.x);
        float vx1 = fmaf(wx, f1.y - f1.x, f1.x);
        float v   = fmaf(wy, vx1 - vx0, vx0);
        float lv  = fmaf(wl, fl.y - fl.x, fl.x);
        r.y = v * lv;
    }
    return r;
}

// 8 threads per point; thread j handles channels 2j, 2j+1 end-to-end.
// Per point: ONE fully-consumed 128B plane line (1 wf), one 8B line-tap load,
// one 8B store (coalesced to 256B/warp). 2 tasks/thread, loads front-batched.
__global__ void __launch_bounds__(128, 9) sample_kernel(
    const float2* __restrict__ coords_plane,   // (3, N)
    const float2* __restrict__ coords_line,    // (3, N)
    float2* __restrict__ out)                  // (3, N, 16) as float2[3N*8]
{
    unsigned base = blockIdx.x * 128u + threadIdx.x;   // < 3*N*4
    const unsigned HALF = 3u * NPTS * 4u;              // id stride between tasks

    unsigned qA, lA, qB, lB;
    float wxA, wyA, wlA, wxB, wyB, wlB;
    decode(base, coords_plane, coords_line, qA, lA, wxA, wyA, wlA);
    decode(base + HALF, coords_plane, coords_line, qB, lB, wxB, wyB, wlB);

    const uint4* Q = reinterpret_cast<const uint4*>(g_quad);
    const uint2* L = reinterpret_cast<const uint2*>(g_lineq);

    // ---- issue all 4 texel loads (planes bypass L1; lines stay L1-hot) ----
    uint4 qa = __ldcg(Q + qA);
    uint4 qb = __ldcg(Q + qB);
    uint2 la = __ldg(L + lA);
    uint2 lb = __ldg(L + lB);

    // ---- compute + store ----
    __stcs(&out[base], combine(qa, la, wxA, wyA, wlA));
    __stcs(&out[base + HALF], combine(qb, lb, wxB, wyB, wlB));
}

extern "C" void kernel_launch(void* const* d_in, const int* in_sizes, int n_in,
                              void* d_out, int out_size) {
    const float* coords_plane = (const float*)d_in[0];
    const float* coords_line  = (const float*)d_in[1];
    const float* plane_xy     = (const float*)d_in[2];
    const float* plane_yz     = (const float*)d_in[3];
    const float* plane_xz     = (const float*)d_in[4];
    const float* line_x       = (const float*)d_in[5];
    const float* line_y       = (const float*)d_in[6];
    const float* line_z       = (const float*)d_in[7];
    float* out = (float*)d_out;

    {
        int total = 3 * PLANE + 3 * DIM;
        int block = 256;
        int grid = (total + block - 1) / block;
        build_kernel<<<grid, block>>>(plane_xy, plane_yz, plane_xz,
                                      line_x, line_y, line_z);
    }
    {
        unsigned threads_total = 3u * NPTS * 4u;   // 12,582,912
        int block = 128;
        int grid = (int)(threads_total / block);   // 98304
        sample_kernel<<<grid, block>>>(
            reinterpret_cast<const float2*>(coords_plane),
            reinterpret_cast<const float2*>(coords_line),
            reinterpret_cast<float2*>(out));
    }
}

// round 11
// speedup vs baseline: 1.4085x; 1.4085x over previous
#include <cuda_runtime.h>
#include <cuda_fp16.h>

#define DIM 300
#define C 16
#define NPTS 1048576u   // 2^20
#define PLANE (DIM * DIM)

// Pair-interleaved fp16 scratch (x-neighbor pre-clamped at build time).
// Plane block (o, y, x): 32 halves = 16 ch of __half2{ v[y][x], v[y][min(x+1,DIM-1)] }.
// Line  block (o, j):    32 halves = 16 ch of __half2{ v[j],    v[min(j+1,DIM-1)] }.
// o=0 -> (plane_yz, line_x), o=1 -> (plane_xz, line_y), o=2 -> (plane_xy, line_z)
__device__ __align__(128) __half g_plane_p[3 * PLANE * 2 * C];   // 17.28 MB
__device__ __align__(128) __half g_line_p[3 * DIM * 2 * C];      // 57.6 KB

__global__ void transpose_kernel(const float* __restrict__ pxy,
                                 const float* __restrict__ pyz,
                                 const float* __restrict__ pxz,
                                 const float* __restrict__ lx,
                                 const float* __restrict__ ly,
                                 const float* __restrict__ lz) {
    int id = blockIdx.x * blockDim.x + threadIdx.x;
    if (id < 3 * PLANE) {
        int p = id / PLANE;
        int pos = id - p * PLANE;       // y*DIM + x
        int x = pos % DIM;
        int dx = (x < DIM - 1) ? 1 : 0;
        const float* src = (p == 0) ? pyz : (p == 1) ? pxz : pxy;
        union { __half2 h2[16]; uint4 u[4]; } pk;
#pragma unroll
        for (int c = 0; c < C; c++) {
            float a = __ldg(&src[c * PLANE + pos]);
            float b = __ldg(&src[c * PLANE + pos + dx]);
            pk.h2[c] = __floats2half2_rn(a, b);
        }
        uint4* dst = reinterpret_cast<uint4*>(g_plane_p + (size_t)(p * PLANE + pos) * 2 * C);
#pragma unroll
        for (int j = 0; j < 4; j++) dst[j] = pk.u[j];
    } else if (id < 3 * PLANE + 3 * DIM) {
        int r = id - 3 * PLANE;
        int p = r / DIM;
        int pos = r - p * DIM;
        int dx = (pos < DIM - 1) ? 1 : 0;
        const float* src = (p == 0) ? lx : (p == 1) ? ly : lz;
        union { __half2 h2[16]; uint4 u[4]; } pk;
#pragma unroll
        for (int c = 0; c < C; c++) {
            float a = __ldg(&src[c * DIM + pos]);
            float b = __ldg(&src[c * DIM + pos + dx]);
            pk.h2[c] = __floats2half2_rn(a, b);
        }
        uint4* dst = reinterpret_cast<uint4*>(g_line_p + (size_t)(p * DIM + pos) * 2 * C);
#pragma unroll
        for (int j = 0; j < 4; j++) dst[j] = pk.u[j];
    }
}

__device__ __forceinline__ float4 combine(uint4 r0, uint4 r1, uint4 lr,
                                          float wx, float wy, float wl) {
    const __half2* h0 = reinterpret_cast<const __half2*>(&r0);
    const __half2* h1 = reinterpret_cast<const __half2*>(&r1);
    const __half2* hl = reinterpret_cast<const __half2*>(&lr);
    float res[4];
#pragma unroll
    for (int i = 0; i < 4; i++) {
        float2 f0 = __half22float2(h0[i]);   // (v[y0][x0], v[y0][x1])
        float2 f1 = __half22float2(h1[i]);   // (v[y1][x0], v[y1][x1])
        float2 fl2 = __half22float2(hl[i]);  // (l[j0], l[j1])
        float vx0 = fmaf(wx, f0.y - f0.x, f0.x);
        float vx1 = fmaf(wx, f1.y - f1.x, f1.x);
        float v   = fmaf(wy, vx1 - vx0, vx0);
        float lv  = fmaf(wl, fl2.y - fl2.x, fl2.x);
        res[i] = v * lv;
    }
    return make_float4(res[0], res[1], res[2], res[3]);
}

// Warp-cooperative: each lane decodes ONE point (32 points/warp, coords loads
// fully coalesced), then 4 task-slots of 8 points each pull the owning lane's
// 5 params via shfl.idx. No redundant decode; wavefront structure = R6.
// No clamps: coords strictly in [-1,1) => x0,y0,j0 <= DIM-2; "+1" x/j neighbor
// pre-clamped in scratch.
__global__ void __launch_bounds__(128, 9) sample_kernel(
    const float2* __restrict__ coords_plane,   // (3, N)
    const float2* __restrict__ coords_line,    // (3, N)
    float4* __restrict__ out)                  // (3, N, 4) float4
{
    unsigned warp = (blockIdx.x * 128u + threadIdx.x) >> 5;   // < 3N/32
    unsigned lane = threadIdx.x & 31u;

    // ---- decode this lane's point ----
    unsigned mypt = warp * 32u + lane;        // point-output id, < 3N
    unsigned o = mypt >> 20;
    unsigned n = mypt & (NPTS - 1u);
    unsigned po = (o == 2u) ? 0u : o + 1u;

    float2 pc = __ldg(&coords_plane[po * NPTS + n]);
    float2 lc = __ldg(&coords_line[o * NPTS + n]);

    const float S = 0.5f * (DIM - 1);
    float ix = fmaf(pc.x, S, S);
    float iy = fmaf(pc.y, S, S);
    int x0 = (int)ix;                 // trunc == floor (ix >= 0)
    int y0 = (int)iy;
    float wx = ix - (float)x0;
    float wy = iy - (float)y0;
    unsigned pb = o * (unsigned)(PLANE * 4) + (unsigned)(y0 * DIM + x0) * 4u;

    float iyl = fmaf(lc.y, S, S);
    int j0 = (int)iyl;
    float wl = iyl - (float)j0;
    unsigned lb = o * (unsigned)(DIM * 4) + (unsigned)j0 * 4u;

    unsigned q = lane & 3u;
    unsigned sub = lane >> 2;                 // point-within-slot 0..7
    unsigned outbase = warp * 128u + lane;    // float4 units; +32 per slot

    const uint4* P = reinterpret_cast<const uint4*>(g_plane_p);
    const uint4* L = reinterpret_cast<const uint4*>(g_line_p);

    // ---- slots 0,1: gather params, front-batch 6 loads, combine ----
    unsigned s0 = sub, s1 = 8u + sub;
    unsigned p0 = __shfl_sync(0xffffffffu, pb, s0) + q;
    unsigned l0 = __shfl_sync(0xffffffffu, lb, s0) + q;
    float wx0 = __shfl_sync(0xffffffffu, wx, s0);
    float wy0 = __shfl_sync(0xffffffffu, wy, s0);
    float wl0 = __shfl_sync(0xffffffffu, wl, s0);
    unsigned p1 = __shfl_sync(0xffffffffu, pb, s1) + q;
    unsigned l1 = __shfl_sync(0xffffffffu, lb, s1) + q;
    float wx1 = __shfl_sync(0xffffffffu, wx, s1);
    float wy1 = __shfl_sync(0xffffffffu, wy, s1);
    float wl1 = __shfl_sync(0xffffffffu, wl, s1);

    uint4 a0 = __ldcg(P + p0);
    uint4 a1 = __ldcg(P + p0 + DIM * 4);
    uint4 b0 = __ldcg(P + p1);
    uint4 b1 = __ldcg(P + p1 + DIM * 4);
    uint4 la = __ldg(L + l0);
    uint4 lbv = __ldg(L + l1);

    __stcs(&out[outbase], combine(a0, a1, la, wx0, wy0, wl0));
    __stcs(&out[outbase + 32u], combine(b0, b1, lbv, wx1, wy1, wl1));

    // ---- slots 2,3 ----
    unsigned s2 = 16u + sub, s3 = 24u + sub;
    unsigned p2 = __shfl_sync(0xffffffffu, pb, s2) + q;
    unsigned l2 = __shfl_sync(0xffffffffu, lb, s2) + q;
    float wx2 = __shfl_sync(0xffffffffu, wx, s2);
    float wy2 = __shfl_sync(0xffffffffu, wy, s2);
    float wl2 = __shfl_sync(0xffffffffu, wl, s2);
    unsigned p3 = __shfl_sync(0xffffffffu, pb, s3) + q;
    unsigned l3 = __shfl_sync(0xffffffffu, lb, s3) + q;
    float wx3 = __shfl_sync(0xffffffffu, wx, s3);
    float wy3 = __shfl_sync(0xffffffffu, wy, s3);
    float wl3 = __shfl_sync(0xffffffffu, wl, s3);

    uint4 c0 = __ldcg(P + p2);
    uint4 c1 = __ldcg(P + p2 + DIM * 4);
    uint4 d0 = __ldcg(P + p3);
    uint4 d1 = __ldcg(P + p3 + DIM * 4);
    uint4 lc2 = __ldg(L + l2);
    uint4 ld3 = __ldg(L + l3);

    __stcs(&out[outbase + 64u], combine(c0, c1, lc2, wx2, wy2, wl2));
    __stcs(&out[outbase + 96u], combine(d0, d1, ld3, wx3, wy3, wl3));
}

extern "C" void kernel_launch(void* const* d_in, const int* in_sizes, int n_in,
                              void* d_out, int out_size) {
    const float* coords_plane = (const float*)d_in[0];
    const float* coords_line  = (const float*)d_in[1];
    const float* plane_xy     = (const float*)d_in[2];
    const float* plane_yz     = (const float*)d_in[3];
    const float* plane_xz     = (const float*)d_in[4];
    const float* line_x       = (const float*)d_in[5];
    const float* line_y       = (const float*)d_in[6];
    const float* line_z       = (const float*)d_in[7];
    float* out = (float*)d_out;

    {
        int total = 3 * PLANE + 3 * DIM;
        int block = 256;
        int grid = (total + block - 1) / block;
        transpose_kernel<<<grid, block>>>(plane_xy, plane_yz, plane_xz,
                                          line_x, line_y, line_z);
    }
    {
        unsigned threads_total = 3u * NPTS;        // one lane decodes one point
        int block = 128;
        int grid = (int)(threads_total / block);   // 24576
        sample_kernel<<<grid, block>>>(
            reinterpret_cast<const float2*>(coords_plane),
            reinterpret_cast<const float2*>(coords_line),
            reinterpret_cast<float4*>(out));
    }
}